// round 2
// baseline (speedup 1.0000x reference)
#include <cuda_runtime.h>
#include <cstdint>
#include <math.h>

#define NNI   32
#define CCI   256
#define HWI   1024
#define NPIX  (NNI*HWI)     // 32768 pixels
#define NBORD 124           // border pixels per image
#define NCHK  36            // 2304/64 chunks

// ---------------- static device scratch (no runtime allocation) ----------------
__device__ uint32_t           g_X32[2][NPIX*8];            // sign bits, channel-packed per pixel (8 u32 = 256 ch)
__device__ uint32_t           g_Wc32[2][CCI*72];           // weights channel-packed: [o][k*8+q2]
__device__ unsigned long long g_Wp64[2][CCI*NCHK];         // weights patch-flat:     [o][chunk]
__device__ unsigned long long g_Vm[HWI*NCHK];              // validity mask per (h,w) per chunk
__device__ unsigned long long g_Xp[2][NNI*NBORD*NCHK];     // border pixels, patch-flat bits
__device__ short              g_acc[2][NNI*CCI*HWI];       // conv outputs (clipped)
__device__ long long          g_S[2*CCI];                  // bn1 int stats (sum,sumsq)/ch
__device__ double             g_Dd[2*CCI];                 // bn2 dbl stats /ch
__device__ float              g_coef[4*CCI];               // A1,B1,A2,B2

// ---------------- helpers ----------------
__device__ __forceinline__ void border_hw(int b, int& h, int& w){
    if (b < 32)       { h = 0;  w = b; }
    else if (b < 64)  { h = 31; w = b - 32; }
    else              { int r = b - 64; h = 1 + (r >> 1); w = (r & 1) ? 31 : 0; }
}
__device__ __forceinline__ long long warp_red_ll(long long v){
    for (int d = 16; d; d >>= 1) v += __shfl_down_sync(0xffffffffu, v, d);
    return v;
}
__device__ __forceinline__ double warp_red_d(double v){
    for (int d = 16; d; d >>= 1) v += __shfl_down_sync(0xffffffffu, v, d);
    return v;
}
__device__ __forceinline__ int warp_red_i(int v){
    for (int d = 16; d; d >>= 1) v += __shfl_down_sync(0xffffffffu, v, d);
    return v;
}

// ---------------- zero the atomic accumulators (needed every graph replay) ----------------
__global__ void k_zero(){
    int t = threadIdx.x;
    if (t < 2*CCI){ g_S[t] = 0; g_Dd[t] = 0.0; }
}

// ---------------- pack weights (both layouts). grid <<<256,128>>> ----------------
__global__ void k_pack_w(const float* __restrict__ w, int which){
    int o = blockIdx.x, t = threadIdx.x;
    if (t < 72){
        int k = t >> 3, q2 = t & 7;
        uint32_t bits = 0;
        for (int b = 0; b < 32; b++){
            int c = q2*32 + b;
            bits |= (uint32_t)(w[(size_t)(o*CCI + c)*9 + k] >= 0.f) << b;
        }
        g_Wc32[which][o*72 + t] = bits;
    } else if (t < 72 + NCHK){
        int j = t - 72;
        unsigned long long bits = 0ull;
        for (int b = 0; b < 64; b++){
            int f = 64*j + b;
            int c = f / 9, k = f - 9*c;
            bits |= (unsigned long long)(w[(size_t)(o*CCI + c)*9 + k] >= 0.f) << b;
        }
        g_Wp64[which][o*NCHK + j] = bits;
    }
}

// ---------------- validity masks. grid <<<1024,36>>> ----------------
__global__ void k_vmask(){
    int hw = blockIdx.x, j = threadIdx.x;
    int h = hw >> 5, w = hw & 31;
    unsigned long long m = 0ull;
    for (int b = 0; b < 64; b++){
        int f  = 64*j + b;
        int k  = f % 9;
        int kh = k / 3, kw = k % 3;
        int hh = h + kh - 1, ww = w + kw - 1;
        if ((unsigned)hh < 32u && (unsigned)ww < 32u) m |= 1ull << b;
    }
    g_Vm[hw*NCHK + j] = m;
}

// ---------------- pack x0 sign bits. grid <<<128,256>>> ----------------
__global__ void k_pack_x1(const float* __restrict__ x){
    int p = blockIdx.x*blockDim.x + threadIdx.x;
    if (p >= NPIX) return;
    int n = p >> 10, hw = p & 1023;
    const float* src = x + (size_t)n*CCI*HWI + hw;
    uint32_t wd[8] = {0,0,0,0,0,0,0,0};
    for (int c = 0; c < CCI; c++){
        uint32_t bit = (src[(size_t)c*HWI] >= 0.f);
        wd[c >> 5] |= bit << (c & 31);
    }
    #pragma unroll
    for (int q = 0; q < 8; q++) g_X32[0][p*8 + q] = wd[q];
}

// ---------------- pack sign(bn1(acc1)) bits. grid <<<128,256>>> ----------------
__global__ void k_pack_x2(){
    int p = blockIdx.x*blockDim.x + threadIdx.x;
    if (p >= NPIX) return;
    int n = p >> 10, hw = p & 1023;
    uint32_t wd[8] = {0,0,0,0,0,0,0,0};
    for (int c = 0; c < CCI; c++){
        float v = (float)g_acc[0][(size_t)(n*CCI + c)*HWI + hw];
        float z = g_coef[c]*v + g_coef[CCI + c];
        uint32_t bit = (z >= 0.f);
        wd[c >> 5] |= bit << (c & 31);
    }
    #pragma unroll
    for (int q = 0; q < 8; q++) g_X32[1][p*8 + q] = wd[q];
}

// ---------------- assemble patch-flat words for border pixels. grid <<<NNI*NBORD,64>>> ----------------
__global__ void k_border_pack(int which){
    int blk = blockIdx.x;
    int n = blk / NBORD, b = blk % NBORD;
    int h, w; border_hw(b, h, w);
    int j = threadIdx.x;
    if (j >= NCHK) return;
    unsigned long long bits = 0ull;
    for (int bb = 0; bb < 64; bb++){
        int f  = 64*j + bb;
        int c  = f / 9, k = f - 9*c;
        int kh = k / 3, kw = k % 3;
        int hh = h + kh - 1, ww = w + kw - 1;
        if ((unsigned)hh < 32u && (unsigned)ww < 32u){
            uint32_t word = g_X32[which][(((n*32 + hh)*32 + ww) << 3) + (c >> 5)];
            bits |= (unsigned long long)((word >> (c & 31)) & 1u) << bb;
        }
    }
    g_Xp[which][(size_t)(n*NBORD + b)*NCHK + j] = bits;
}

// ---------------- interior conv: XNOR-popcount. grid <<<NNI*30*2,256>>> ----------------
__global__ void __launch_bounds__(256) k_conv_int(int which){
    __shared__ uint32_t sw[128*72];   // 128 output channels' weights
    __shared__ uint32_t sx[3*256];    // 3 input rows (32 px * 8 words)
    int blk   = blockIdx.x;
    int ohalf = blk & 1;
    int nh    = blk >> 1;
    int n = nh / 30, h = 1 + nh % 30;
    int t = threadIdx.x;

    for (int i = t; i < 128*72; i += 256) sw[i] = g_Wc32[which][ohalf*128*72 + i];
    {
        const uint32_t* base = &g_X32[which][((size_t)(n*32 + (h-1))*32) * 8];
        for (int i = t; i < 3*256; i += 256) sx[i] = base[i];
    }
    __syncthreads();

    int wq = t & 31;          // output column
    int og = t >> 5;          // o-group (8 groups x 16 o)
    if (wq < 1 || wq > 30) return;

    uint32_t xr[72];
    #pragma unroll
    for (int kh = 0; kh < 3; kh++)
        #pragma unroll
        for (int kw = 0; kw < 3; kw++)
            #pragma unroll
            for (int q = 0; q < 8; q++)
                xr[(kh*3 + kw)*8 + q] = sx[kh*256 + (wq + kw - 1)*8 + q];

    short* dst = &g_acc[which][(size_t)n*CCI*HWI + h*32 + wq];
    for (int i = 0; i < 16; i++){
        int o_local = og*16 + i;
        const uint32_t* wr = &sw[o_local*72];
        int mm = 0;
        #pragma unroll
        for (int u = 0; u < 72; u++) mm += __popc(xr[u] ^ wr[u]);
        int D = 2304 - 2*mm;
        D = D < -254 ? -254 : (D > 254 ? 254 : D);
        int o = ohalf*128 + o_local;
        dst[(size_t)o*HWI] = (short)D;
    }
}

// ---------------- border conv: per-chunk quantized psums. grid <<<NNI*NBORD,256>>> ----------------
__global__ void k_conv_border(int which){
    __shared__ unsigned long long sxp[NCHK], svm[NCHK];
    __shared__ int svc[NCHK];
    int blk = blockIdx.x;
    int n = blk / NBORD, b = blk % NBORD;
    int h, w; border_hw(b, h, w);
    int t = threadIdx.x;
    if (t < NCHK){
        sxp[t] = g_Xp[which][(size_t)(n*NBORD + b)*NCHK + t];
        unsigned long long m = g_Vm[(h*32 + w)*NCHK + t];
        svm[t] = m;
        svc[t] = __popcll(m);
    }
    __syncthreads();
    int o = t;
    const unsigned long long* wp = &g_Wp64[which][o*NCHK];
    int acc = 0;
    #pragma unroll
    for (int j = 0; j < NCHK; j++){
        int mm = __popcll((sxp[j] ^ wp[j]) & svm[j]);
        int ps = svc[j] - 2*mm;
        // round-half-even of ps/2 times 2: ps even -> ps; ps odd -> nearest multiple of 4
        acc += ps + ((ps & 1) ? ((ps & 2) - 1) : 0);
    }
    acc = acc < -254 ? -254 : (acc > 254 ? 254 : acc);
    g_acc[which][(size_t)(n*CCI + o)*HWI + h*32 + w] = (short)acc;
}

// ---------------- bn1 integer stats. grid <<<NNI*CCI,256>>> ----------------
__global__ void k_bn1_stats(){
    int blk = blockIdx.x;                 // n*CCI + c
    int c = blk & (CCI - 1);
    const short* src = &g_acc[0][(size_t)blk*HWI];
    int t = threadIdx.x;
    int s = 0, q = 0;
    for (int i = t; i < HWI; i += 256){ int v = src[i]; s += v; q += v*v; }
    __shared__ long long shs[8], shq[8];
    long long sl = warp_red_ll((long long)s);
    long long ql = warp_red_ll((long long)q);
    if ((t & 31) == 0){ shs[t >> 5] = sl; shq[t >> 5] = ql; }
    __syncthreads();
    if (t == 0){
        long long S = 0, Q = 0;
        for (int i = 0; i < 8; i++){ S += shs[i]; Q += shq[i]; }
        atomicAdd((unsigned long long*)&g_S[2*c],     (unsigned long long)S);
        atomicAdd((unsigned long long*)&g_S[2*c + 1], (unsigned long long)Q);
    }
}

// ---------------- bn1 coefficients. <<<1,256>>> ----------------
__global__ void k_coef1(const float* __restrict__ gamma, const float* __restrict__ beta){
    int c = threadIdx.x;
    double s = (double)g_S[2*c], q = (double)g_S[2*c + 1];
    const double Nn = (double)(NNI*HWI);
    double m   = s / Nn;
    double var = q / Nn - m*m;
    double rs  = 1.0 / sqrt(var + 1e-5);
    double A   = rs * (double)gamma[c];
    g_coef[c]       = (float)A;
    g_coef[CCI + c] = (float)((double)beta[c] - m*A);
}

// ---------------- bn2 double stats over clip(acc2)+x0. grid <<<NNI*CCI,256>>> ----------------
__global__ void k_bn2_stats(const float* __restrict__ x0){
    int blk = blockIdx.x;
    int c = blk & (CCI - 1);
    const short* a2 = &g_acc[1][(size_t)blk*HWI];
    const float* xs = x0 + (size_t)blk*HWI;
    int t = threadIdx.x;
    double s = 0.0, q = 0.0;
    for (int i = t; i < HWI; i += 256){
        double y = (double)a2[i] + (double)xs[i];
        s += y; q += y*y;
    }
    __shared__ double shs[8], shq[8];
    s = warp_red_d(s); q = warp_red_d(q);
    if ((t & 31) == 0){ shs[t >> 5] = s; shq[t >> 5] = q; }
    __syncthreads();
    if (t == 0){
        double S = 0, Q = 0;
        for (int i = 0; i < 8; i++){ S += shs[i]; Q += shq[i]; }
        atomicAdd(&g_Dd[2*c], S);
        atomicAdd(&g_Dd[2*c + 1], Q);
    }
}

// ---------------- bn2 coefficients. <<<1,256>>> ----------------
__global__ void k_coef2(const float* __restrict__ gamma, const float* __restrict__ beta){
    int c = threadIdx.x;
    double s = g_Dd[2*c], q = g_Dd[2*c + 1];
    const double Nn = (double)(NNI*HWI);
    double m   = s / Nn;
    double var = q / Nn - m*m;
    double rs  = 1.0 / sqrt(var + 1e-5);
    double A   = rs * (double)gamma[c];
    g_coef[2*CCI + c] = (float)A;
    g_coef[3*CCI + c] = (float)((double)beta[c] - m*A);
}

// ---------------- final: bn2 + hardtanh. grid <<<NNI*CCI,256>>> ----------------
__global__ void k_final(const float* __restrict__ x0, float* __restrict__ out){
    int blk = blockIdx.x;
    int c = blk & (CCI - 1);
    float A = g_coef[2*CCI + c], B = g_coef[3*CCI + c];
    const short* a2 = &g_acc[1][(size_t)blk*HWI];
    const float* xs = x0 + (size_t)blk*HWI;
    float* dst = out + (size_t)blk*HWI;
    for (int i = threadIdx.x; i < HWI; i += 256){
        float y = (float)a2[i] + xs[i];
        float z = A*y + B;
        z = fminf(1.f, fmaxf(-1.f, z));
        dst[i] = z;
    }
}

// ---------------- regularizer (geometry only). <<<1,256>>> ----------------
__global__ void k_reg(const float* __restrict__ reg0, float* __restrict__ out, int out_size){
    int t = threadIdx.x;
    int cnt = 0;
    for (int i = t; i < HWI*NCHK; i += 256) cnt += (int)(__popcll(g_Vm[i]) & 1ull);
    __shared__ int sh[8];
    cnt = warp_red_i(cnt);
    if ((t & 31) == 0) sh[t >> 5] = cnt;
    __syncthreads();
    if (t == 0){
        int T = 0;
        for (int i = 0; i < 8; i++) T += sh[i];
        // reg = reg0 + r1 + 2*r2, r1 == r2 == T/1024
        out[out_size - 1] = reg0[0] + 3.0f * (float)T / 1024.0f;
    }
}

// ---------------- launch ----------------
extern "C" void kernel_launch(void* const* d_in, const int* in_sizes, int n_in,
                              void* d_out, int out_size){
    const float* x0     = (const float*)d_in[0];
    const float* reg0   = (const float*)d_in[1];
    const float* w1     = (const float*)d_in[2];
    const float* gamma1 = (const float*)d_in[3];
    const float* beta1  = (const float*)d_in[4];
    const float* w2     = (const float*)d_in[5];
    const float* gamma2 = (const float*)d_in[6];
    const float* beta2  = (const float*)d_in[7];
    float* out = (float*)d_out;

    k_zero<<<1, 512>>>();
    k_pack_w<<<256, 128>>>(w1, 0);
    k_pack_w<<<256, 128>>>(w2, 1);
    k_vmask<<<HWI, NCHK>>>();
    k_pack_x1<<<128, 256>>>(x0);

    // conv1
    k_border_pack<<<NNI*NBORD, 64>>>(0);
    k_conv_int<<<NNI*30*2, 256>>>(0);
    k_conv_border<<<NNI*NBORD, 256>>>(0);

    // bn1 -> sign threshold -> repack
    k_bn1_stats<<<NNI*CCI, 256>>>();
    k_coef1<<<1, 256>>>(gamma1, beta1);
    k_pack_x2<<<128, 256>>>();

    // conv2
    k_border_pack<<<NNI*NBORD, 64>>>(1);
    k_conv_int<<<NNI*30*2, 256>>>(1);
    k_conv_border<<<NNI*NBORD, 256>>>(1);

    // bn2 over clip(acc2)+x0, then final clamp
    k_bn2_stats<<<NNI*CCI, 256>>>(x0);
    k_coef2<<<1, 256>>>(gamma2, beta2);
    k_final<<<NNI*CCI, 256>>>(x0, out);

    k_reg<<<1, 256>>>(reg0, out, out_size);
}